// round 1
// baseline (speedup 1.0000x reference)
#include <cuda_runtime.h>

// GNN layer: out = MLP_n([nf | segsum(MLP_e([nf[s]|nf[d]|ef]))])
// Decomposition:
//   A|B = nf @ [We1_rows0:128 | We1_rows128:256]   (per node, 256+256)
//   C   = ef @ We1_rows256:320                     (per edge, 256)
//   per edge-dir: h = A[s]+B[d]+C[e]; msg = leaky(h) @ We2; RED into red[d]
//   hn  = leaky([nf|red] @ Wn1); out = hn @ Wn2

constexpr int NN_MAX = 100000;
constexpr int NE_MAX = 500000;
constexpr float NEG = 0.01f;

__device__ __align__(128) float g_AB[(size_t)NN_MAX * 512];
__device__ __align__(128) float g_C[(size_t)NE_MAX * 256];
__device__ __align__(128) float g_red[(size_t)NN_MAX * 128];
__device__ __align__(128) float g_hn[(size_t)NN_MAX * 256];

__device__ __forceinline__ float lky(float x) { return x >= 0.0f ? x : NEG * x; }

__device__ __forceinline__ void red_add_v4(float* addr, float4 v) {
    asm volatile("red.global.add.v4.f32 [%0], {%1,%2,%3,%4};"
                 :: "l"(addr), "f"(v.x), "f"(v.y), "f"(v.z), "f"(v.w) : "memory");
}

__global__ void zero_kernel(float4* __restrict__ p, int n4) {
    int i = blockIdx.x * blockDim.x + threadIdx.x;
    if (i < n4) p[i] = make_float4(0.f, 0.f, 0.f, 0.f);
}

// Generic tiled GEMM: out[row, 0:N] = act(X[row, 0:K] @ W[K, N])
// CONCAT: X row = [X1 row (128 floats) | X2 row (128 floats)], K must be 256.
// 256 threads/CTA. Cols per thread: 4. Rows per thread: 8.
template <int K, int N, bool CONCAT, bool LEAKY>
__global__ void gemm_k(const float* __restrict__ X1, const float* __restrict__ X2,
                       const float* __restrict__ W, float* __restrict__ out,
                       int M, int out_stride) {
    constexpr int CT = N / 4;        // threads spanning the N cols
    constexpr int RG = 256 / CT;     // row groups
    constexpr int TR = RG * 8;       // tile rows
    constexpr int K4 = K / 4;
    extern __shared__ float xs[];    // TR * K floats

    const int tid = threadIdx.x;
    const int row0 = blockIdx.x * TR;

    // ---- load input tile (zero-pad out-of-range rows) ----
    for (int idx = tid; idx < TR * K4; idx += 256) {
        int r = idx / K4, k4 = idx % K4;
        int row = row0 + r;
        float4 v = make_float4(0.f, 0.f, 0.f, 0.f);
        if (row < M) {
            if (CONCAT) {
                v = (k4 < 32) ? ((const float4*)X1)[(long)row * 32 + k4]
                              : ((const float4*)X2)[(long)row * 32 + (k4 - 32)];
            } else {
                v = ((const float4*)X1)[(long)row * K4 + k4];
            }
        }
        *(float4*)&xs[r * K + k4 * 4] = v;
    }
    __syncthreads();

    const int tx = tid % CT, ty = tid / CT;
    const int c = tx * 4;

    float4 acc[8];
#pragma unroll
    for (int i = 0; i < 8; i++) acc[i] = make_float4(0.f, 0.f, 0.f, 0.f);

    for (int k = 0; k < K; k += 4) {
        float4 w0 = __ldg((const float4*)&W[(k + 0) * N + c]);
        float4 w1 = __ldg((const float4*)&W[(k + 1) * N + c]);
        float4 w2 = __ldg((const float4*)&W[(k + 2) * N + c]);
        float4 w3 = __ldg((const float4*)&W[(k + 3) * N + c]);
#pragma unroll
        for (int i = 0; i < 8; i++) {
            float4 h = *(const float4*)&xs[(ty * 8 + i) * K + k];
            acc[i].x = fmaf(h.x, w0.x, fmaf(h.y, w1.x, fmaf(h.z, w2.x, fmaf(h.w, w3.x, acc[i].x))));
            acc[i].y = fmaf(h.x, w0.y, fmaf(h.y, w1.y, fmaf(h.z, w2.y, fmaf(h.w, w3.y, acc[i].y))));
            acc[i].z = fmaf(h.x, w0.z, fmaf(h.y, w1.z, fmaf(h.z, w2.z, fmaf(h.w, w3.z, acc[i].z))));
            acc[i].w = fmaf(h.x, w0.w, fmaf(h.y, w1.w, fmaf(h.z, w2.w, fmaf(h.w, w3.w, acc[i].w))));
        }
    }

#pragma unroll
    for (int i = 0; i < 8; i++) {
        int row = row0 + ty * 8 + i;
        if (row < M) {
            float4 v = acc[i];
            if (LEAKY) { v.x = lky(v.x); v.y = lky(v.y); v.z = lky(v.z); v.w = lky(v.w); }
            *(float4*)&out[(long)row * out_stride + c] = v;
        }
    }
}

// Edge kernel: 64 edge-directions per CTA.
//   h[r][0:256] = leaky(A[s] + B[d] + C[e])   (gathered into smem)
//   msg[64][128] = h @ We2
//   red.global.add.v4 msg rows into g_red[d]
__global__ void edge_kernel(const float* __restrict__ AB, const float* __restrict__ C,
                            const float* __restrict__ W2,
                            const int* __restrict__ src, const int* __restrict__ dst,
                            float* __restrict__ red, int E) {
    extern __shared__ float hs[];       // 64 * 256 floats = 64 KB
    __shared__ int ddst[64];

    const int tid = threadIdx.x;
    const int warp = tid / 32, lane = tid % 32;
    const long base = (long)blockIdx.x * 64;
    const long twoE = 2L * E;

    // ---- gather + sum + leaky: each warp loads its 8 rows ----
#pragma unroll
    for (int i = 0; i < 8; i++) {
        int r = warp * 8 + i;
        long edir = base + r;
        if (edir >= twoE) { if (lane == 0) ddst[r] = -1; continue; }
        bool rev = edir >= E;
        int e = rev ? (int)(edir - E) : (int)edir;
        int se = src[e], de = dst[e];
        int s = rev ? de : se;
        int d = rev ? se : de;
        if (lane == 0) ddst[r] = d;
        const float4* Arow = (const float4*)AB + (long)s * 128;       // A part: f4 0..63
        const float4* Brow = (const float4*)AB + (long)d * 128 + 64;  // B part: f4 64..127
        const float4* Crow = (const float4*)C + (long)e * 64;
#pragma unroll
        for (int t = 0; t < 2; t++) {
            int k4 = lane + t * 32;
            float4 a = Arow[k4];
            float4 b = Brow[k4];
            float4 cc = Crow[k4];
            float4 h;
            h.x = lky(a.x + b.x + cc.x);
            h.y = lky(a.y + b.y + cc.y);
            h.z = lky(a.z + b.z + cc.z);
            h.w = lky(a.w + b.w + cc.w);
            *(float4*)&hs[r * 256 + k4 * 4] = h;
        }
    }
    __syncthreads();

    // ---- GEMM: rows warp*8..warp*8+7, cols lane*4..lane*4+3, K=256 ----
    const int c = lane * 4;
    float4 acc[8];
#pragma unroll
    for (int i = 0; i < 8; i++) acc[i] = make_float4(0.f, 0.f, 0.f, 0.f);

    for (int k = 0; k < 256; k += 4) {
        float4 w0 = __ldg((const float4*)&W2[(k + 0) * 128 + c]);
        float4 w1 = __ldg((const float4*)&W2[(k + 1) * 128 + c]);
        float4 w2 = __ldg((const float4*)&W2[(k + 2) * 128 + c]);
        float4 w3 = __ldg((const float4*)&W2[(k + 3) * 128 + c]);
#pragma unroll
        for (int i = 0; i < 8; i++) {
            float4 h = *(const float4*)&hs[(warp * 8 + i) * 256 + k];
            acc[i].x = fmaf(h.x, w0.x, fmaf(h.y, w1.x, fmaf(h.z, w2.x, fmaf(h.w, w3.x, acc[i].x))));
            acc[i].y = fmaf(h.x, w0.y, fmaf(h.y, w1.y, fmaf(h.z, w2.y, fmaf(h.w, w3.y, acc[i].y))));
            acc[i].z = fmaf(h.x, w0.z, fmaf(h.y, w1.z, fmaf(h.z, w2.z, fmaf(h.w, w3.z, acc[i].z))));
            acc[i].w = fmaf(h.x, w0.w, fmaf(h.y, w1.w, fmaf(h.z, w2.w, fmaf(h.w, w3.w, acc[i].w))));
        }
    }

    // ---- scatter-add ----
#pragma unroll
    for (int i = 0; i < 8; i++) {
        int r = warp * 8 + i;
        int d = ddst[r];
        if (d >= 0) red_add_v4(&red[(long)d * 128 + c], acc[i]);
    }
}

extern "C" void kernel_launch(void* const* d_in, const int* in_sizes, int n_in,
                              void* d_out, int out_size) {
    const float* nf  = (const float*)d_in[0];
    const float* ef  = (const float*)d_in[1];
    const int*   src = (const int*)d_in[2];
    const int*   dst = (const int*)d_in[3];
    const float* We1 = (const float*)d_in[4];   // (320, 256)
    const float* We2 = (const float*)d_in[5];   // (256, 128)
    const float* Wn1 = (const float*)d_in[6];   // (256, 256)
    const float* Wn2 = (const float*)d_in[7];   // (256, 128)

    const int N = in_sizes[0] / 128;
    const int E = in_sizes[2];

    float *AB, *C, *red, *hn;
    cudaGetSymbolAddress((void**)&AB, g_AB);
    cudaGetSymbolAddress((void**)&C, g_C);
    cudaGetSymbolAddress((void**)&red, g_red);
    cudaGetSymbolAddress((void**)&hn, g_hn);

    cudaFuncSetAttribute((const void*)edge_kernel,
                         cudaFuncAttributeMaxDynamicSharedMemorySize, 64 * 256 * 4);
    cudaFuncSetAttribute((const void*)gemm_k<256, 128, false, false>,
                         cudaFuncAttributeMaxDynamicSharedMemorySize, 64 * 256 * 4);

    // 0) zero the segment-sum accumulator
    int n4 = N * 128 / 4;
    zero_kernel<<<(n4 + 255) / 256, 256>>>((float4*)red, n4);

    // 1) A = nf @ We1[0:128,:]   -> g_AB cols [0,256), stride 512
    gemm_k<128, 256, false, false><<<(N + 31) / 32, 256, 32 * 128 * 4>>>(
        nf, nullptr, We1, AB, N, 512);
    // 2) B = nf @ We1[128:256,:] -> g_AB cols [256,512)
    gemm_k<128, 256, false, false><<<(N + 31) / 32, 256, 32 * 128 * 4>>>(
        nf, nullptr, We1 + 128 * 256, AB + 256, N, 512);
    // 3) C = ef @ We1[256:320,:]
    gemm_k<64, 256, false, false><<<(E + 31) / 32, 256, 32 * 64 * 4>>>(
        ef, nullptr, We1 + 256 * 256, C, E, 256);
    // 4) edge message GEMM + scatter-add
    long twoE = 2L * E;
    edge_kernel<<<(int)((twoE + 63) / 64), 256, 64 * 256 * 4>>>(
        AB, C, We2, src, dst, red, E);
    // 5) hn = leaky([nf | red] @ Wn1)
    gemm_k<256, 256, true, true><<<(N + 31) / 32, 256, 32 * 256 * 4>>>(
        nf, red, Wn1, hn, N, 256);
    // 6) out = hn @ Wn2
    gemm_k<256, 128, false, false><<<(N + 63) / 64, 256, 64 * 256 * 4>>>(
        hn, nullptr, Wn2, (float*)d_out, N, 128);
}